// round 12
// baseline (speedup 1.0000x reference)
#include <cuda_runtime.h>
#include <cuda_fp16.h>
#include <math.h>

#define B_ 32
#define T_ 64
#define N_ 32
#define D_ 128
#define E_ 8
#define K_ 2

typedef unsigned long long u64;
typedef unsigned int u32;

// SMEM u32-unit offsets
#define OFF_XA  0        // x     [64][68]  half2 (d-pairs)
#define OFF_KS  4352     // K     [64][68]  half2 (dc-pairs)
#define OFF_VT  8704     // V^T   [128][36] half2 (t-pairs)
#define OFF_PS  13312    // P     [2][64][36] half2 (kt-pairs)
#define OFF_OS  17920    // O     [64][68]  half2   (S overlays OS+O1)
#define OFF_O1  22272    // O1    [64][68]  half2
#define OFF_WS  26624    // Wslab ping-pong: 2 bufs x 5120 u32
#define SMEM_U  36864    // *4 = 147456 bytes

__device__ int   d_eidx[B_][K_];
__device__ float d_gateg[B_][K_];
__device__ float d_part[B_][32][D_];

// Pre-converted fp16 weights in staging layout
__device__ u32 WdT_g[8 * 32 * 4 * 5120];   // ~21 MB
__device__ u32 WsT_g[16 * 4 * 2560];       // 640 KB

__device__ __forceinline__ u64 fpack(float lo, float hi) {
    u64 d; asm("mov.b64 %0, {%1, %2};" : "=l"(d) : "f"(lo), "f"(hi)); return d;
}
__device__ __forceinline__ u32 h2pack(float lo, float hi) {
    __half2 h = __floats2half2_rn(lo, hi);
    return *(u32*)&h;
}
__device__ __forceinline__ void mma_f16(float* c, const u32* a, u32 b0, u32 b1) {
    asm volatile(
        "mma.sync.aligned.m16n8k16.row.col.f32.f16.f16.f32 "
        "{%0,%1,%2,%3}, {%4,%5,%6,%7}, {%8,%9}, {%0,%1,%2,%3};\n"
        : "+f"(c[0]), "+f"(c[1]), "+f"(c[2]), "+f"(c[3])
        : "r"(a[0]), "r"(a[1]), "r"(a[2]), "r"(a[3]), "r"(b0), "r"(b1));
}
__device__ __forceinline__ void ldsm4(u32* r, u32 saddr) {
    asm volatile("ldmatrix.sync.aligned.m8n8.x4.shared.b16 {%0,%1,%2,%3}, [%4];"
        : "=r"(r[0]), "=r"(r[1]), "=r"(r[2]), "=r"(r[3]) : "r"(saddr));
}
__device__ __forceinline__ void cp16(u32 smem_addr, const void* gptr) {
    asm volatile("cp.async.cg.shared.global [%0], [%1], 16;" :: "r"(smem_addr), "l"(gptr));
}
#define CP_COMMIT() asm volatile("cp.async.commit_group;")

// ---------------------------------------------------------------------------
// Prep: convert fp32 weights -> fp16 half2 staging layout
// ---------------------------------------------------------------------------
__global__ void prep_kernel(const float* __restrict__ Wd,
                            const float* __restrict__ Ws) {
    __shared__ float tile[32][129];
    const int bid = blockIdx.x;
    const int tid = threadIdx.x;   // 256
    const float* src;
    u32* dst;
    if (bid < 2048) {
        const int s = bid & 3, mat = (bid >> 2) & 1, n = (bid >> 3) & 31, e = bid >> 8;
        src = Wd + ((size_t)(e * 2 + mat) * 32 + n) * (128 * 128) + s * 32 * 128;
        dst = WdT_g + ((size_t)((e * 32 + n) * 4 + s)) * 5120 + mat * 2560;
    } else {
        const int r = bid - 2048;
        const int s = r & 3, em = r >> 2;
        src = Ws + (size_t)em * (128 * 128) + s * 32 * 128;
        dst = WsT_g + ((size_t)em * 4 + s) * 2560;
    }
    #pragma unroll
    for (int i = tid; i < 4096; i += 256)
        tile[i >> 7][i & 127] = src[i];
    __syncthreads();
    for (int j = tid; j < 2560; j += 256) {
        const int c = j / 20, d2 = j % 20;
        u32 v = 0;
        if (d2 < 16) v = h2pack(tile[2 * d2][c], tile[2 * d2 + 1][c]);
        dst[j] = v;
    }
}

// ---------------------------------------------------------------------------
// Gating
// ---------------------------------------------------------------------------
__global__ void gate_partial(const float* __restrict__ x) {
    const int b   = blockIdx.y;
    const int ch  = blockIdx.x;
    const int tid = threadIdx.x;
    const float* base = x + ((size_t)b * T_ * N_ + ch * 64) * D_;
    float s = 0.f;
    #pragma unroll 8
    for (int r = 0; r < 64; ++r) s += base[r * D_ + tid];
    d_part[b][ch][tid] = s;
}

__global__ void gate_kernel(const float* __restrict__ Wg) {
    const int b   = blockIdx.x;
    const int tid = threadIdx.x;
    __shared__ float smean[D_];
    __shared__ float slog[E_];

    float s = 0.f;
    #pragma unroll
    for (int c = 0; c < 32; ++c) s += d_part[b][c][tid];
    smean[tid] = s * (1.0f / (float)(T_ * N_));
    __syncthreads();

    if (tid < E_) {
        float l = 0.f;
        for (int d = 0; d < D_; ++d) l += smean[d] * Wg[d * E_ + tid];
        slog[tid] = l;
    }
    __syncthreads();

    if (tid == 0) {
        int i0 = 0; float v0 = slog[0];
        for (int e = 1; e < E_; ++e) if (slog[e] > v0) { v0 = slog[e]; i0 = e; }
        int i1 = -1; float v1 = -3.0e38f;
        for (int e = 0; e < E_; ++e) if (e != i0 && slog[e] > v1) { v1 = slog[e]; i1 = e; }
        const float e1  = expf(v1 - v0);
        const float inv = 1.0f / (1.0f + e1);
        d_eidx[b][0]  = i0; d_eidx[b][1]  = i1;
        d_gateg[b][0] = inv; d_gateg[b][1] = e1 * inv;
    }
}

// ---------------------------------------------------------------------------
// Kernel 2: fp16 mma + ldmatrix fragment loads + cp.async weight staging
// ---------------------------------------------------------------------------
__global__ __launch_bounds__(512, 1)
void moe_kernel(const float* __restrict__ x,
                const float* __restrict__ bd,
                const float* __restrict__ bs,
                float* __restrict__ out) {
    extern __shared__ u32 smu[];
    u32*   XA = smu + OFF_XA;
    u32*   KS = smu + OFF_KS;
    u32*   VT = smu + OFF_VT;
    u32*   PS = smu + OFF_PS;
    u32*   OS = smu + OFF_OS;
    u32*   O1 = smu + OFF_O1;
    u32*   WS = smu + OFF_WS;
    float* S  = (float*)(smu + OFF_OS);

    const u32 xa_s = (u32)__cvta_generic_to_shared(XA);
    const u32 ks_s = (u32)__cvta_generic_to_shared(KS);
    const u32 vt_s = (u32)__cvta_generic_to_shared(VT);
    const u32 ps_s = (u32)__cvta_generic_to_shared(PS);
    const u32 os_s = (u32)__cvta_generic_to_shared(OS);
    const u32 o1_s = (u32)__cvta_generic_to_shared(O1);
    const u32 ws_s = (u32)__cvta_generic_to_shared(WS);

    const int n    = blockIdx.x;
    const int b    = blockIdx.y;
    const int tid  = threadIdx.x;
    const int lane = tid & 31;
    const int wid  = tid >> 5;
    const int g    = lane >> 2;
    const int tq   = lane & 3;
    const int lr   = lane & 15;          // ldmatrix row within 16
    const int lc   = (lane >> 4) << 2;   // ldmatrix chunk select (u32)

    // ---- load x -> XA half2 ----
    {
        const float4* xg = (const float4*)(x + ((size_t)b * T_ * N_ + n) * D_);
        #pragma unroll
        for (int i = tid; i < T_ * D_ / 4; i += 512) {
            const int t  = i >> 5;
            const int c2 = (i & 31) * 2;
            float4 v = xg[(size_t)t * (N_ * D_ / 4) + (i & 31)];
            XA[t * 68 + c2]     = h2pack(v.x, v.y);
            XA[t * 68 + c2 + 1] = h2pack(v.z, v.w);
        }
    }

    // mappings
    const int matId = wid >> 3;
    const int k_m0  = (wid & 3) * 16;
    const int k_n0  = ((wid >> 2) & 1) * 64;
    const int v_m0  = (wid & 7) * 16;
    const int h     = wid >> 3;
    const int a_m0  = (wid & 3) * 16;
    const int a_n0  = ((wid >> 2) & 1) * 32;
    const int hb2   = h * 32;
    const int g2_m0 = (wid & 3) * 16;
    const int g2_n0 = (wid >> 2) * 32;

    // ldmatrix base addresses (bytes)
    const u32 aK_b = xa_s + 4u * ((k_m0 + lr) * 68 + lc);
    const u32 bK_b = ws_s + 4u * ((k_n0 + lr) * 20 + lc);
    const u32 aV_b = ws_s + 4u * (2560 + (v_m0 + lr) * 20 + lc);
    const u32 bV_b = xa_s + 4u * (lr * 68 + lc);
    const u32 aA_b = xa_s + 4u * ((a_m0 + lr) * 68 + hb2 + lc);
    const u32 bA_b = ks_s + 4u * ((a_n0 + lr) * 68 + hb2 + lc);
    const u32 aP_b = ps_s + 4u * (h * 2304 + (a_m0 + lr) * 36 + lc);
    const u32 bP_b = vt_s + 4u * ((h * 64 + a_n0 + lr) * 36 + lc);
    const u32 aO_b = os_s + 4u * ((g2_m0 + lr) * 68 + lc);
    const u32 aO1_b = o1_s + 4u * ((g2_m0 + lr) * 68 + lc);
    const u32 bW_b = ws_s + 4u * ((g2_n0 + lr) * 20 + lc);

    float accv[4][4];
    #pragma unroll
    for (int ni = 0; ni < 4; ++ni)
        #pragma unroll
        for (int c = 0; c < 4; ++c) accv[ni][c] = 0.f;

    for (int slot = 0; slot < K_; ++slot) {
        const int   e  = d_eidx[b][slot];
        const float gg = d_gateg[b][slot];

        // =================== GEMM1 ===================
        {
            const u32* wdsrc = WdT_g + ((size_t)(e * 32 + n) * 4) * 5120;

            float acc[8][4];
            if (matId == 0) {
                const float* bm = bd + ((size_t)(e * 2 + 0) * N_ + n) * D_;
                #pragma unroll
                for (int ni = 0; ni < 8; ++ni) {
                    const float b0v = bm[k_n0 + 8 * ni + 2 * tq];
                    const float b1v = bm[k_n0 + 8 * ni + 2 * tq + 1];
                    acc[ni][0] = b0v; acc[ni][1] = b1v; acc[ni][2] = b0v; acc[ni][3] = b1v;
                }
            } else {
                const float* bm = bd + ((size_t)(e * 2 + 1) * N_ + n) * D_;
                const float blo = bm[v_m0 + g];
                const float bhi = bm[v_m0 + 8 + g];
                #pragma unroll
                for (int ni = 0; ni < 8; ++ni) {
                    acc[ni][0] = blo; acc[ni][1] = blo; acc[ni][2] = bhi; acc[ni][3] = bhi;
                }
            }
            #pragma unroll
            for (int j = tid; j < 1280; j += 512)
                cp16(ws_s + (u32)(j * 16), wdsrc + j * 4);
            CP_COMMIT();
            for (int s = 0; s < 4; ++s) {
                const u32 buf = (u32)((s & 1) * 20480);
                if (s < 3) {
                    const u32 boff = (u32)(((s + 1) & 1) * 20480);
                    const u32* src = wdsrc + (s + 1) * 5120;
                    #pragma unroll
                    for (int j = tid; j < 1280; j += 512)
                        cp16(ws_s + boff + (u32)(j * 16), src + j * 4);
                    CP_COMMIT();
                    asm volatile("cp.async.wait_group 1;");
                } else {
                    asm volatile("cp.async.wait_group 0;");
                }
                __syncthreads();
                #pragma unroll
                for (int kk = 0; kk < 2; ++kk) {
                    if (matId == 0) {
                        u32 a[4];
                        ldsm4(a, aK_b + (u32)(s * 64 + kk * 32));
                        #pragma unroll
                        for (int nip = 0; nip < 4; ++nip) {
                            u32 bf[4];
                            ldsm4(bf, bK_b + buf + (u32)(nip * 1280 + kk * 32));
                            mma_f16(acc[2 * nip],     a, bf[0], bf[2]);
                            mma_f16(acc[2 * nip + 1], a, bf[1], bf[3]);
                        }
                    } else {
                        u32 a[4];
                        ldsm4(a, aV_b + buf + (u32)(kk * 32));
                        #pragma unroll
                        for (int nip = 0; nip < 4; ++nip) {
                            u32 bf[4];
                            ldsm4(bf, bV_b + (u32)(nip * 4352 + s * 64 + kk * 32));
                            mma_f16(acc[2 * nip],     a, bf[0], bf[2]);
                            mma_f16(acc[2 * nip + 1], a, bf[1], bf[3]);
                        }
                    }
                }
                __syncthreads();
            }
            if (matId == 0) {
                #pragma unroll
                for (int ni = 0; ni < 8; ++ni) {
                    KS[(k_m0 + g)     * 68 + k_n0 / 2 + 4 * ni + tq] = h2pack(acc[ni][0], acc[ni][1]);
                    KS[(k_m0 + 8 + g) * 68 + k_n0 / 2 + 4 * ni + tq] = h2pack(acc[ni][2], acc[ni][3]);
                }
            } else {
                #pragma unroll
                for (int ni = 0; ni < 8; ++ni) {
                    VT[(v_m0 + g)     * 36 + 4 * ni + tq] = h2pack(acc[ni][0], acc[ni][1]);
                    VT[(v_m0 + 8 + g) * 36 + 4 * ni + tq] = h2pack(acc[ni][2], acc[ni][3]);
                }
            }
            __syncthreads();
        }

        // =================== att: S = Q K^T / 8 ===================
        {
            float sa[4][4];
            #pragma unroll
            for (int ni = 0; ni < 4; ++ni)
                #pragma unroll
                for (int c = 0; c < 4; ++c) sa[ni][c] = 0.f;
            #pragma unroll
            for (int ks = 0; ks < 4; ++ks) {
                u32 a[4];
                ldsm4(a, aA_b + (u32)(ks * 32));
                #pragma unroll
                for (int nip = 0; nip < 2; ++nip) {
                    u32 bf[4];
                    ldsm4(bf, bA_b + (u32)(nip * 4352 + ks * 32));
                    mma_f16(sa[2 * nip],     a, bf[0], bf[2]);
                    mma_f16(sa[2 * nip + 1], a, bf[1], bf[3]);
                }
            }
            float* Sh = S + h * 4352;
            #pragma unroll
            for (int ni = 0; ni < 4; ++ni) {
                const int cc = a_n0 + 8 * ni + 2 * tq;
                *(u64*)&Sh[(a_m0 + g)     * 68 + cc] = fpack(0.125f * sa[ni][0], 0.125f * sa[ni][1]);
                *(u64*)&Sh[(a_m0 + 8 + g) * 68 + cc] = fpack(0.125f * sa[ni][2], 0.125f * sa[ni][3]);
            }
            __syncthreads();
        }

        // =================== softmax -> P (half) ===================
        {
            __half* Pb = (__half*)PS;
            #pragma unroll
            for (int j = 0; j < 8; ++j) {
                const int r  = wid * 8 + j;
                const int hh = r >> 6;
                const int t  = r & 63;
                float* row = S + hh * 4352 + t * 68;
                const float a0 = row[lane];
                const float a1 = row[lane + 32];
                float m = fmaxf(a0, a1);
                #pragma unroll
                for (int o = 16; o > 0; o >>= 1) m = fmaxf(m, __shfl_xor_sync(0xffffffffu, m, o));
                const float e0 = __expf(a0 - m);
                const float e1 = __expf(a1 - m);
                float sum = e0 + e1;
                #pragma unroll
                for (int o = 16; o > 0; o >>= 1) sum += __shfl_xor_sync(0xffffffffu, sum, o);
                const float inv = 1.0f / sum;
                __half* Ph = Pb + hh * 4608 + t * 72;
                Ph[lane]      = __float2half_rn(e0 * inv);
                Ph[lane + 32] = __float2half_rn(e1 * inv);
            }
            __syncthreads();
        }

        // =================== O = P V ===================
        {
            float oa[4][4];
            #pragma unroll
            for (int ni = 0; ni < 4; ++ni)
                #pragma unroll
                for (int c = 0; c < 4; ++c) oa[ni][c] = 0.f;
            #pragma unroll
            for (int ks = 0; ks < 4; ++ks) {
                u32 a[4];
                ldsm4(a, aP_b + (u32)(ks * 32));
                #pragma unroll
                for (int nip = 0; nip < 2; ++nip) {
                    u32 bf[4];
                    ldsm4(bf, bP_b + (u32)(nip * 2304 + ks * 32));
                    mma_f16(oa[2 * nip],     a, bf[0], bf[2]);
                    mma_f16(oa[2 * nip + 1], a, bf[1], bf[3]);
                }
            }
            __syncthreads();   // S reads done before OS overwrite (overlay!)
            #pragma unroll
            for (int ni = 0; ni < 4; ++ni) {
                const int c2 = h * 32 + a_n0 / 2 + 4 * ni + tq;
                OS[(a_m0 + g)     * 68 + c2] = h2pack(oa[ni][0], oa[ni][1]);
                OS[(a_m0 + 8 + g) * 68 + c2] = h2pack(oa[ni][2], oa[ni][3]);
            }
            __syncthreads();
        }

        // =================== GEMM2: O1 = relu(O @ Ws0 + bs0) ===================
        {
            const u32* wssrc = WsT_g + (size_t)(e * 2 + 0) * 4 * 2560;
            const float* bsp = bs + (e * 2 + 0) * D_;
            float acc[4][4];
            #pragma unroll
            for (int ni = 0; ni < 4; ++ni) {
                const float b0v = bsp[g2_n0 + 8 * ni + 2 * tq];
                const float b1v = bsp[g2_n0 + 8 * ni + 2 * tq + 1];
                acc[ni][0] = b0v; acc[ni][1] = b1v; acc[ni][2] = b0v; acc[ni][3] = b1v;
            }
            #pragma unroll
            for (int j = tid; j < 640; j += 512)
                cp16(ws_s + (u32)(j * 16), wssrc + j * 4);
            CP_COMMIT();
            for (int s = 0; s < 4; ++s) {
                const u32 buf = (u32)((s & 1) * 20480);
                if (s < 3) {
                    const u32 boff = (u32)(((s + 1) & 1) * 20480);
                    const u32* src = wssrc + (s + 1) * 2560;
                    #pragma unroll
                    for (int j = tid; j < 640; j += 512)
                        cp16(ws_s + boff + (u32)(j * 16), src + j * 4);
                    CP_COMMIT();
                    asm volatile("cp.async.wait_group 1;");
                } else {
                    asm volatile("cp.async.wait_group 0;");
                }
                __syncthreads();
                #pragma unroll
                for (int kk = 0; kk < 2; ++kk) {
                    u32 a[4];
                    ldsm4(a, aO_b + (u32)(s * 64 + kk * 32));
                    #pragma unroll
                    for (int nip = 0; nip < 2; ++nip) {
                        u32 bf[4];
                        ldsm4(bf, bW_b + buf + (u32)(nip * 1280 + kk * 32));
                        mma_f16(acc[2 * nip],     a, bf[0], bf[2]);
                        mma_f16(acc[2 * nip + 1], a, bf[1], bf[3]);
                    }
                }
                __syncthreads();
            }
            #pragma unroll
            for (int ni = 0; ni < 4; ++ni) {
                const int c2 = g2_n0 / 2 + 4 * ni + tq;
                O1[(g2_m0 + g)     * 68 + c2] = h2pack(fmaxf(acc[ni][0], 0.f), fmaxf(acc[ni][1], 0.f));
                O1[(g2_m0 + 8 + g) * 68 + c2] = h2pack(fmaxf(acc[ni][2], 0.f), fmaxf(acc[ni][3], 0.f));
            }
        }

        // =================== GEMM3: out_e = O1 @ Ws1 + bs1 ; accv += g*exp ===================
        {
            const u32* wssrc = WsT_g + (size_t)(e * 2 + 1) * 4 * 2560;
            const float* bsp = bs + (e * 2 + 1) * D_;
            float acc[4][4];
            #pragma unroll
            for (int ni = 0; ni < 4; ++ni) {
                const float b0v = bsp[g2_n0 + 8 * ni + 2 * tq];
                const float b1v = bsp[g2_n0 + 8 * ni + 2 * tq + 1];
                acc[ni][0] = b0v; acc[ni][1] = b1v; acc[ni][2] = b0v; acc[ni][3] = b1v;
            }
            #pragma unroll
            for (int j = tid; j < 640; j += 512)
                cp16(ws_s + (u32)(j * 16), wssrc + j * 4);
            CP_COMMIT();
            __syncthreads();   // orders O1 stores before compute reads
            for (int s = 0; s < 4; ++s) {
                const u32 buf = (u32)((s & 1) * 20480);
                if (s < 3) {
                    const u32 boff = (u32)(((s + 1) & 1) * 20480);
                    const u32* src = wssrc + (s + 1) * 2560;
                    #pragma unroll
                    for (int j = tid; j < 640; j += 512)
                        cp16(ws_s + boff + (u32)(j * 16), src + j * 4);
                    CP_COMMIT();
                    asm volatile("cp.async.wait_group 1;");
                } else {
                    asm volatile("cp.async.wait_group 0;");
                }
                __syncthreads();
                #pragma unroll
                for (int kk = 0; kk < 2; ++kk) {
                    u32 a[4];
                    ldsm4(a, aO1_b + (u32)(s * 64 + kk * 32));
                    #pragma unroll
                    for (int nip = 0; nip < 2; ++nip) {
                        u32 bf[4];
                        ldsm4(bf, bW_b + buf + (u32)(nip * 1280 + kk * 32));
                        mma_f16(acc[2 * nip],     a, bf[0], bf[2]);
                        mma_f16(acc[2 * nip + 1], a, bf[1], bf[3]);
                    }
                }
                __syncthreads();
            }
            #pragma unroll
            for (int ni = 0; ni < 4; ++ni)
                #pragma unroll
                for (int c = 0; c < 4; ++c)
                    accv[ni][c] += gg * __expf(acc[ni][c]);
        }
    }

    // ---- combine epilogue ----
    const float EPSF = 2.2204460492503131e-16f;
    #pragma unroll
    for (int ni = 0; ni < 4; ++ni) {
        const int cc  = g2_n0 + 8 * ni + 2 * tq;
        const int t0r = g2_m0 + g;
        const int t1r = g2_m0 + 8 + g;
        float v0 = accv[ni][0]; if (v0 == 0.f) v0 = EPSF;
        float v1 = accv[ni][1]; if (v1 == 0.f) v1 = EPSF;
        float v2 = accv[ni][2]; if (v2 == 0.f) v2 = EPSF;
        float v3 = accv[ni][3]; if (v3 == 0.f) v3 = EPSF;
        *(u64*)&out[(((size_t)b * T_ + t0r) * N_ + n) * D_ + cc] = fpack(__logf(v0), __logf(v1));
        *(u64*)&out[(((size_t)b * T_ + t1r) * N_ + n) * D_ + cc] = fpack(__logf(v2), __logf(v3));
    }
}

// ---------------------------------------------------------------------------
// launcher
// ---------------------------------------------------------------------------
extern "C" void kernel_launch(void* const* d_in, const int* in_sizes, int n_in,
                              void* d_out, int out_size) {
    const float* x  = (const float*)d_in[0];
    const float* Wg = (const float*)d_in[1];
    const float* Wd = (const float*)d_in[2];
    const float* bd = (const float*)d_in[3];
    const float* Ws = (const float*)d_in[4];
    const float* bs = (const float*)d_in[5];
    float* out = (float*)d_out;

    const int smem_bytes = SMEM_U * 4; // 147456 B
    cudaFuncSetAttribute(moe_kernel, cudaFuncAttributeMaxDynamicSharedMemorySize, smem_bytes);

    prep_kernel<<<2112, 256>>>(Wd, Ws);
    dim3 pgrid(32, B_);
    gate_partial<<<pgrid, 128>>>(x);
    gate_kernel<<<B_, 128>>>(Wg);
    dim3 grid(N_, B_);
    moe_kernel<<<grid, 512, smem_bytes>>>(x, bd, bs, out);
}

// round 13
// speedup vs baseline: 1.6374x; 1.6374x over previous
#include <cuda_runtime.h>
#include <cuda_fp16.h>
#include <math.h>

#define B_ 32
#define T_ 64
#define N_ 32
#define D_ 128
#define E_ 8
#define K_ 2

typedef unsigned long long u64;
typedef unsigned int u32;

// SMEM u32-unit offsets
#define OFF_XA  0        // x     [64][68]  half2 (d-pairs)
#define OFF_KS  4352     // K     [64][68]  half2 (dc-pairs)
#define OFF_VT  8704     // V^T   [128][36] half2 (t-pairs)
#define OFF_PS  13312    // P     [2][64][36] half2 (kt-pairs)
#define OFF_OS  17920    // O     [64][68]  half2   (S overlays OS+O1)
#define OFF_O1  22272    // O1    [64][68]  half2
#define OFF_WS  26624    // weight buffer: 20480 u32 (all 4 slabs)
#define SMEM_U  47104    // *4 = 188416 bytes

__device__ int   d_eidx[B_][K_];
__device__ float d_gateg[B_][K_];
__device__ float d_part[B_][32][D_];

// Pre-converted fp16 weights in staging layout
__device__ u32 WdT_g[8 * 32 * 4 * 5120];   // ~21 MB
__device__ u32 WsT_g[16 * 4 * 2560];       // 640 KB

__device__ __forceinline__ u64 fpack(float lo, float hi) {
    u64 d; asm("mov.b64 %0, {%1, %2};" : "=l"(d) : "f"(lo), "f"(hi)); return d;
}
__device__ __forceinline__ u32 h2pack(float lo, float hi) {
    __half2 h = __floats2half2_rn(lo, hi);
    return *(u32*)&h;
}
__device__ __forceinline__ void mma_f16(float* c, const u32* a, const u32* b) {
    asm volatile(
        "mma.sync.aligned.m16n8k16.row.col.f32.f16.f16.f32 "
        "{%0,%1,%2,%3}, {%4,%5,%6,%7}, {%8,%9}, {%0,%1,%2,%3};\n"
        : "+f"(c[0]), "+f"(c[1]), "+f"(c[2]), "+f"(c[3])
        : "r"(a[0]), "r"(a[1]), "r"(a[2]), "r"(a[3]), "r"(b[0]), "r"(b[1]));
}
__device__ __forceinline__ void cp16(u32 smem_addr, const void* gptr) {
    asm volatile("cp.async.cg.shared.global [%0], [%1], 16;" :: "r"(smem_addr), "l"(gptr));
}
#define CP_COMMIT() asm volatile("cp.async.commit_group;")
#define CP_WAIT0()  asm volatile("cp.async.wait_group 0;")

// ---------------------------------------------------------------------------
// Prep: convert fp32 weights -> fp16 half2 staging layout
// ---------------------------------------------------------------------------
__global__ void prep_kernel(const float* __restrict__ Wd,
                            const float* __restrict__ Ws) {
    __shared__ float tile[32][129];
    const int bid = blockIdx.x;
    const int tid = threadIdx.x;   // 256
    const float* src;
    u32* dst;
    if (bid < 2048) {
        const int s = bid & 3, mat = (bid >> 2) & 1, n = (bid >> 3) & 31, e = bid >> 8;
        src = Wd + ((size_t)(e * 2 + mat) * 32 + n) * (128 * 128) + s * 32 * 128;
        dst = WdT_g + ((size_t)((e * 32 + n) * 4 + s)) * 5120 + mat * 2560;
    } else {
        const int r = bid - 2048;
        const int s = r & 3, em = r >> 2;
        src = Ws + (size_t)em * (128 * 128) + s * 32 * 128;
        dst = WsT_g + ((size_t)em * 4 + s) * 2560;
    }
    #pragma unroll
    for (int i = tid; i < 4096; i += 256)
        tile[i >> 7][i & 127] = src[i];
    __syncthreads();
    for (int j = tid; j < 2560; j += 256) {
        const int c = j / 20, d2 = j % 20;
        u32 v = 0;
        if (d2 < 16) v = h2pack(tile[2 * d2][c], tile[2 * d2 + 1][c]);
        dst[j] = v;
    }
}

// ---------------------------------------------------------------------------
// Gating
// ---------------------------------------------------------------------------
__global__ void gate_partial(const float* __restrict__ x) {
    const int b   = blockIdx.y;
    const int ch  = blockIdx.x;
    const int tid = threadIdx.x;
    const float* base = x + ((size_t)b * T_ * N_ + ch * 64) * D_;
    float s = 0.f;
    #pragma unroll 8
    for (int r = 0; r < 64; ++r) s += base[r * D_ + tid];
    d_part[b][ch][tid] = s;
}

__global__ void gate_kernel(const float* __restrict__ Wg) {
    const int b   = blockIdx.x;
    const int tid = threadIdx.x;
    __shared__ float smean[D_];
    __shared__ float slog[E_];

    float s = 0.f;
    #pragma unroll
    for (int c = 0; c < 32; ++c) s += d_part[b][c][tid];
    smean[tid] = s * (1.0f / (float)(T_ * N_));
    __syncthreads();

    if (tid < E_) {
        float l = 0.f;
        for (int d = 0; d < D_; ++d) l += smean[d] * Wg[d * E_ + tid];
        slog[tid] = l;
    }
    __syncthreads();

    if (tid == 0) {
        int i0 = 0; float v0 = slog[0];
        for (int e = 1; e < E_; ++e) if (slog[e] > v0) { v0 = slog[e]; i0 = e; }
        int i1 = -1; float v1 = -3.0e38f;
        for (int e = 0; e < E_; ++e) if (e != i0 && slog[e] > v1) { v1 = slog[e]; i1 = e; }
        const float e1  = expf(v1 - v0);
        const float inv = 1.0f / (1.0f + e1);
        d_eidx[b][0]  = i0; d_eidx[b][1]  = i1;
        d_gateg[b][0] = inv; d_gateg[b][1] = e1 * inv;
    }
}

// ---------------------------------------------------------------------------
// Kernel 2: fp16 mma + scalar fragment loads (R11 datapath) + whole-weight
// cp.async staging: all 4 slabs at once, prefetched across phases.
// ---------------------------------------------------------------------------
__global__ __launch_bounds__(512, 1)
void moe_kernel(const float* __restrict__ x,
                const float* __restrict__ bd,
                const float* __restrict__ bs,
                float* __restrict__ out) {
    extern __shared__ u32 smu[];
    u32*   XA = smu + OFF_XA;
    u32*   KS = smu + OFF_KS;
    u32*   VT = smu + OFF_VT;
    u32*   PS = smu + OFF_PS;
    u32*   OS = smu + OFF_OS;
    u32*   O1 = smu + OFF_O1;
    u32*   WS = smu + OFF_WS;
    float* S  = (float*)(smu + OFF_OS);

    const u32 ws_s = (u32)__cvta_generic_to_shared(WS);

    const int n    = blockIdx.x;
    const int b    = blockIdx.y;
    const int tid  = threadIdx.x;
    const int lane = tid & 31;
    const int wid  = tid >> 5;
    const int g    = lane >> 2;
    const int tq   = lane & 3;

    // mappings
    const int matId = wid >> 3;
    const int k_m0  = (wid & 3) * 16;
    const int k_n0  = ((wid >> 2) & 1) * 64;
    const int v_m0  = (wid & 7) * 16;
    const int h     = wid >> 3;
    const int a_m0  = (wid & 3) * 16;
    const int a_n0  = ((wid >> 2) & 1) * 32;
    const int g2_m0 = (wid & 3) * 16;
    const int g2_n0 = (wid >> 2) * 32;

    // issue Wd(e0) staging first (overlaps x load)
    {
        const int e0 = d_eidx[b][0];
        const u32* wdsrc = WdT_g + ((size_t)(e0 * 32 + n) * 4) * 5120;
        #pragma unroll
        for (int j = tid; j < 5120; j += 512)
            cp16(ws_s + (u32)(j * 16), wdsrc + j * 4);
        CP_COMMIT();
    }

    // ---- load x -> XA half2 ----
    {
        const float4* xg = (const float4*)(x + ((size_t)b * T_ * N_ + n) * D_);
        #pragma unroll
        for (int i = tid; i < T_ * D_ / 4; i += 512) {
            const int t  = i >> 5;
            const int c2 = (i & 31) * 2;
            float4 v = xg[(size_t)t * (N_ * D_ / 4) + (i & 31)];
            XA[t * 68 + c2]     = h2pack(v.x, v.y);
            XA[t * 68 + c2 + 1] = h2pack(v.z, v.w);
        }
    }

    float accv[4][4];
    #pragma unroll
    for (int ni = 0; ni < 4; ++ni)
        #pragma unroll
        for (int c = 0; c < 4; ++c) accv[ni][c] = 0.f;

    for (int slot = 0; slot < K_; ++slot) {
        const int   e  = d_eidx[b][slot];
        const float gg = d_gateg[b][slot];

        // wait for Wd staging (+ XA stores on slot 0)
        CP_WAIT0();
        __syncthreads();

        // =================== GEMM1: K = x@W0+b0 ; V^T = W1^T@x^T + b1 ===================
        {
            float acc[8][4];
            if (matId == 0) {
                const float* bm = bd + ((size_t)(e * 2 + 0) * N_ + n) * D_;
                #pragma unroll
                for (int ni = 0; ni < 8; ++ni) {
                    const float b0v = bm[k_n0 + 8 * ni + 2 * tq];
                    const float b1v = bm[k_n0 + 8 * ni + 2 * tq + 1];
                    acc[ni][0] = b0v; acc[ni][1] = b1v; acc[ni][2] = b0v; acc[ni][3] = b1v;
                }
            } else {
                const float* bm = bd + ((size_t)(e * 2 + 1) * N_ + n) * D_;
                const float blo = bm[v_m0 + g];
                const float bhi = bm[v_m0 + 8 + g];
                #pragma unroll
                for (int ni = 0; ni < 8; ++ni) {
                    acc[ni][0] = blo; acc[ni][1] = blo; acc[ni][2] = bhi; acc[ni][3] = bhi;
                }
            }
            #pragma unroll
            for (int s = 0; s < 4; ++s) {
                const u32* cur = WS + s * 5120;
                #pragma unroll
                for (int kk = 0; kk < 2; ++kk) {
                    const int d2g = s * 16 + kk * 8;
                    if (matId == 0) {
                        u32 a[4];
                        a[0] = XA[(k_m0 + g)     * 68 + d2g + tq];
                        a[1] = XA[(k_m0 + 8 + g) * 68 + d2g + tq];
                        a[2] = XA[(k_m0 + g)     * 68 + d2g + tq + 4];
                        a[3] = XA[(k_m0 + 8 + g) * 68 + d2g + tq + 4];
                        #pragma unroll
                        for (int ni = 0; ni < 8; ++ni) {
                            u32 bf[2];
                            bf[0] = cur[(k_n0 + 8 * ni + g) * 20 + kk * 8 + tq];
                            bf[1] = cur[(k_n0 + 8 * ni + g) * 20 + kk * 8 + tq + 4];
                            mma_f16(acc[ni], a, bf);
                        }
                    } else {
                        u32 a[4];
                        a[0] = cur[2560 + (v_m0 + g)     * 20 + kk * 8 + tq];
                        a[1] = cur[2560 + (v_m0 + 8 + g) * 20 + kk * 8 + tq];
                        a[2] = cur[2560 + (v_m0 + g)     * 20 + kk * 8 + tq + 4];
                        a[3] = cur[2560 + (v_m0 + 8 + g) * 20 + kk * 8 + tq + 4];
                        #pragma unroll
                        for (int ni = 0; ni < 8; ++ni) {
                            u32 bf[2];
                            bf[0] = XA[(8 * ni + g) * 68 + d2g + tq];
                            bf[1] = XA[(8 * ni + g) * 68 + d2g + tq + 4];
                            mma_f16(acc[ni], a, bf);
                        }
                    }
                }
            }
            if (matId == 0) {
                #pragma unroll
                for (int ni = 0; ni < 8; ++ni) {
                    KS[(k_m0 + g)     * 68 + k_n0 / 2 + 4 * ni + tq] = h2pack(acc[ni][0], acc[ni][1]);
                    KS[(k_m0 + 8 + g) * 68 + k_n0 / 2 + 4 * ni + tq] = h2pack(acc[ni][2], acc[ni][3]);
                }
            } else {
                #pragma unroll
                for (int ni = 0; ni < 8; ++ni) {
                    VT[(v_m0 + g)     * 36 + 4 * ni + tq] = h2pack(acc[ni][0], acc[ni][1]);
                    VT[(v_m0 + 8 + g) * 36 + 4 * ni + tq] = h2pack(acc[ni][2], acc[ni][3]);
                }
            }
            __syncthreads();
        }

        // prefetch Ws0+Ws1 (20480 contiguous u32) — hides behind att/softmax/PV
        {
            const u32* wssrc = WsT_g + (size_t)(e * 2) * 4 * 2560;
            #pragma unroll
            for (int j = tid; j < 5120; j += 512)
                cp16(ws_s + (u32)(j * 16), wssrc + j * 4);
            CP_COMMIT();
        }

        // =================== att: S = Q K^T / 8 (per head) ===================
        {
            const int hb2 = h * 32;
            float sa[4][4];
            #pragma unroll
            for (int ni = 0; ni < 4; ++ni)
                #pragma unroll
                for (int c = 0; c < 4; ++c) sa[ni][c] = 0.f;
            #pragma unroll
            for (int ks = 0; ks < 4; ++ks) {
                const int d2g = hb2 + ks * 8;
                u32 a[4];
                a[0] = XA[(a_m0 + g)     * 68 + d2g + tq];
                a[1] = XA[(a_m0 + 8 + g) * 68 + d2g + tq];
                a[2] = XA[(a_m0 + g)     * 68 + d2g + tq + 4];
                a[3] = XA[(a_m0 + 8 + g) * 68 + d2g + tq + 4];
                #pragma unroll
                for (int ni = 0; ni < 4; ++ni) {
                    u32 bf[2];
                    bf[0] = KS[(a_n0 + 8 * ni + g) * 68 + d2g + tq];
                    bf[1] = KS[(a_n0 + 8 * ni + g) * 68 + d2g + tq + 4];
                    mma_f16(sa[ni], a, bf);
                }
            }
            float* Sh = S + h * 4352;
            #pragma unroll
            for (int ni = 0; ni < 4; ++ni) {
                const int cc = a_n0 + 8 * ni + 2 * tq;
                *(u64*)&Sh[(a_m0 + g)     * 68 + cc] = fpack(0.125f * sa[ni][0], 0.125f * sa[ni][1]);
                *(u64*)&Sh[(a_m0 + 8 + g) * 68 + cc] = fpack(0.125f * sa[ni][2], 0.125f * sa[ni][3]);
            }
            __syncthreads();
        }

        // =================== softmax -> P (half) ===================
        {
            __half* Pb = (__half*)PS;
            #pragma unroll
            for (int j = 0; j < 8; ++j) {
                const int r  = wid * 8 + j;
                const int hh = r >> 6;
                const int t  = r & 63;
                float* row = S + hh * 4352 + t * 68;
                const float a0 = row[lane];
                const float a1 = row[lane + 32];
                float m = fmaxf(a0, a1);
                #pragma unroll
                for (int o = 16; o > 0; o >>= 1) m = fmaxf(m, __shfl_xor_sync(0xffffffffu, m, o));
                const float e0 = __expf(a0 - m);
                const float e1 = __expf(a1 - m);
                float sum = e0 + e1;
                #pragma unroll
                for (int o = 16; o > 0; o >>= 1) sum += __shfl_xor_sync(0xffffffffu, sum, o);
                const float inv = 1.0f / sum;
                __half* Ph = Pb + hh * 4608 + t * 72;
                Ph[lane]      = __float2half_rn(e0 * inv);
                Ph[lane + 32] = __float2half_rn(e1 * inv);
            }
            __syncthreads();   // S dead after this point
        }

        // =================== O = P V (per head) ===================
        {
            const u32* Pu = PS + h * 2304;
            float oa[4][4];
            #pragma unroll
            for (int ni = 0; ni < 4; ++ni)
                #pragma unroll
                for (int c = 0; c < 4; ++c) oa[ni][c] = 0.f;
            #pragma unroll
            for (int ks = 0; ks < 4; ++ks) {
                const int kt2 = ks * 8;
                u32 a[4];
                a[0] = Pu[(a_m0 + g)     * 36 + kt2 + tq];
                a[1] = Pu[(a_m0 + 8 + g) * 36 + kt2 + tq];
                a[2] = Pu[(a_m0 + g)     * 36 + kt2 + tq + 4];
                a[3] = Pu[(a_m0 + 8 + g) * 36 + kt2 + tq + 4];
                #pragma unroll
                for (int ni = 0; ni < 4; ++ni) {
                    u32 bf[2];
                    bf[0] = VT[(h * 64 + a_n0 + 8 * ni + g) * 36 + kt2 + tq];
                    bf[1] = VT[(h * 64 + a_n0 + 8 * ni + g) * 36 + kt2 + tq + 4];
                    mma_f16(oa[ni], a, bf);
                }
            }
            #pragma unroll
            for (int ni = 0; ni < 4; ++ni) {
                const int c2 = h * 32 + a_n0 / 2 + 4 * ni + tq;
                OS[(a_m0 + g)     * 68 + c2] = h2pack(oa[ni][0], oa[ni][1]);
                OS[(a_m0 + 8 + g) * 68 + c2] = h2pack(oa[ni][2], oa[ni][3]);
            }
            CP_WAIT0();        // Ws staging complete
            __syncthreads();   // OS stores + Ws visible to all
        }

        // =================== GEMM2: O1 = relu(O @ Ws0 + bs0) ===================
        {
            const float* bsp = bs + (e * 2 + 0) * D_;
            float acc[4][4];
            #pragma unroll
            for (int ni = 0; ni < 4; ++ni) {
                const float b0v = bsp[g2_n0 + 8 * ni + 2 * tq];
                const float b1v = bsp[g2_n0 + 8 * ni + 2 * tq + 1];
                acc[ni][0] = b0v; acc[ni][1] = b1v; acc[ni][2] = b0v; acc[ni][3] = b1v;
            }
            #pragma unroll
            for (int s = 0; s < 4; ++s) {
                const u32* cur = WS + s * 2560;
                #pragma unroll
                for (int kk = 0; kk < 2; ++kk) {
                    const int d2g = s * 16 + kk * 8;
                    u32 a[4];
                    a[0] = OS[(g2_m0 + g)     * 68 + d2g + tq];
                    a[1] = OS[(g2_m0 + 8 + g) * 68 + d2g + tq];
                    a[2] = OS[(g2_m0 + g)     * 68 + d2g + tq + 4];
                    a[3] = OS[(g2_m0 + 8 + g) * 68 + d2g + tq + 4];
                    #pragma unroll
                    for (int ni = 0; ni < 4; ++ni) {
                        u32 bf[2];
                        bf[0] = cur[(g2_n0 + 8 * ni + g) * 20 + kk * 8 + tq];
                        bf[1] = cur[(g2_n0 + 8 * ni + g) * 20 + kk * 8 + tq + 4];
                        mma_f16(acc[ni], a, bf);
                    }
                }
            }
            #pragma unroll
            for (int ni = 0; ni < 4; ++ni) {
                const int c2 = g2_n0 / 2 + 4 * ni + tq;
                O1[(g2_m0 + g)     * 68 + c2] = h2pack(fmaxf(acc[ni][0], 0.f), fmaxf(acc[ni][1], 0.f));
                O1[(g2_m0 + 8 + g) * 68 + c2] = h2pack(fmaxf(acc[ni][2], 0.f), fmaxf(acc[ni][3], 0.f));
            }
            __syncthreads();
        }

        // =================== GEMM3: out_e = O1 @ Ws1 + bs1 ; accv += g*exp ===================
        {
            const float* bsp = bs + (e * 2 + 1) * D_;
            float acc[4][4];
            #pragma unroll
            for (int ni = 0; ni < 4; ++ni) {
                const float b0v = bsp[g2_n0 + 8 * ni + 2 * tq];
                const float b1v = bsp[g2_n0 + 8 * ni + 2 * tq + 1];
                acc[ni][0] = b0v; acc[ni][1] = b1v; acc[ni][2] = b0v; acc[ni][3] = b1v;
            }
            #pragma unroll
            for (int s = 0; s < 4; ++s) {
                const u32* cur = WS + 10240 + s * 2560;
                #pragma unroll
                for (int kk = 0; kk < 2; ++kk) {
                    const int d2g = s * 16 + kk * 8;
                    u32 a[4];
                    a[0] = O1[(g2_m0 + g)     * 68 + d2g + tq];
                    a[1] = O1[(g2_m0 + 8 + g) * 68 + d2g + tq];
                    a[2] = O1[(g2_m0 + g)     * 68 + d2g + tq + 4];
                    a[3] = O1[(g2_m0 + 8 + g) * 68 + d2g + tq + 4];
                    #pragma unroll
                    for (int ni = 0; ni < 4; ++ni) {
                        u32 bf[2];
                        bf[0] = cur[(g2_n0 + 8 * ni + g) * 20 + kk * 8 + tq];
                        bf[1] = cur[(g2_n0 + 8 * ni + g) * 20 + kk * 8 + tq + 4];
                        mma_f16(acc[ni], a, bf);
                    }
                }
            }
            #pragma unroll
            for (int ni = 0; ni < 4; ++ni)
                #pragma unroll
                for (int c = 0; c < 4; ++c)
                    accv[ni][c] += gg * __expf(acc[ni][c]);
            __syncthreads();   // WS reads done before next expert's staging
        }

        // issue next expert's Wd staging (overlaps epilogue of loop / next top)
        if (slot + 1 < K_) {
            const int e1 = d_eidx[b][slot + 1];
            const u32* wdsrc = WdT_g + ((size_t)(e1 * 32 + n) * 4) * 5120;
            #pragma unroll
            for (int j = tid; j < 5120; j += 512)
                cp16(ws_s + (u32)(j * 16), wdsrc + j * 4);
            CP_COMMIT();
        }
    }

    // ---- combine epilogue ----
    const float EPSF = 2.2204460492503131e-16f;
    #pragma unroll
    for (int ni = 0; ni < 4; ++ni) {
        const int cc  = g2_n0 + 8 * ni + 2 * tq;
        const int t0r = g2_m0 + g;
        const int t1r = g2_m0 + 8 + g;
        float v0 = accv[ni][0]; if (v0 == 0.f) v0 = EPSF;
        float v1 = accv[ni][1]; if (v1 == 0.f) v1 = EPSF;
        float v2 = accv[ni][2]; if (v2 == 0.f) v2 = EPSF;
        float v3 = accv[ni][3]; if (v3 == 0.f) v3 = EPSF;
        *(u64*)&out[(((size_t)b * T_ + t0r) * N_ + n) * D_ + cc] = fpack(__logf(v0), __logf(v1));
        *(u64*)&out[(((size_t)b * T_ + t1r) * N_ + n) * D_ + cc] = fpack(__logf(v2), __logf(v3));
    }
}

// ---------------------------------------------------------------------------
// launcher
// ---------------------------------------------------------------------------
extern "C" void kernel_launch(void* const* d_in, const int* in_sizes, int n_in,
                              void* d_out, int out_size) {
    const float* x  = (const float*)d_in[0];
    const float* Wg = (const float*)d_in[1];
    const float* Wd = (const float*)d_in[2];
    const float* bd = (const float*)d_in[3];
    const float* Ws = (const float*)d_in[4];
    const float* bs = (const float*)d_in[5];
    float* out = (float*)d_out;

    const int smem_bytes = SMEM_U * 4; // 188416 B
    cudaFuncSetAttribute(moe_kernel, cudaFuncAttributeMaxDynamicSharedMemorySize, smem_bytes);

    prep_kernel<<<2112, 256>>>(Wd, Ws);
    dim3 pgrid(32, B_);
    gate_partial<<<pgrid, 128>>>(x);
    gate_kernel<<<B_, 128>>>(Wg);
    dim3 grid(N_, B_);
    moe_kernel<<<grid, 512, smem_bytes>>>(x, bd, bs, out);
}